// round 2
// baseline (speedup 1.0000x reference)
#include <cuda_runtime.h>

// Problem constants
#define N_ITEMS 20000
#define N_REC   8
#define N_USERS 2048
#define U4_TOT  (N_USERS / 4)        // 512 float4 columns total

// User chunking: 2 chunks of 1024 users (256 float4 cols). Score tile per
// chunk = 20000*1024*4B = 82MB -> fits in 126MB L2.
#define CHUNK_USERS 1024
#define CHUNK_U4    (CHUNK_USERS / 4)   // 256
#define N_CHUNKS    (N_USERS / CHUNK_USERS)

#define ITEMS_PER_BLOCK 25              // grid.y = 800 per chunk

// Scratch: per-user column max (float bits, all scores >= 0) and reciprocal.
__device__ float g_max[N_USERS];
__device__ float g_inv[N_USERS];

__global__ void init_max_kernel() {
    int u = blockIdx.x * blockDim.x + threadIdx.x;
    if (u < N_USERS) g_max[u] = 0.0f;
}

// Pass 1 (per user-chunk): scores[i][u] = sum_r in[i*8+r][u]*w[r].
// Input read with streaming hint (read-once) so the score tile stays in L2.
__global__ void __launch_bounds__(CHUNK_U4) score_max_kernel(
    const float4* __restrict__ in,     // [N_ITEMS*N_REC, U4_TOT]
    const float*  __restrict__ w,      // [8]
    float4*       __restrict__ scores, // [N_ITEMS, U4_TOT]
    int u4_base)                       // chunk column offset in float4 units
{
    const int u4 = u4_base + threadIdx.x;     // one block spans the chunk stripe

    float wr[N_REC];
#pragma unroll
    for (int r = 0; r < N_REC; ++r) wr[r] = __ldg(&w[r]);

    const int i0   = blockIdx.y * ITEMS_PER_BLOCK;
    const int iend = min(i0 + ITEMS_PER_BLOCK, N_ITEMS);

    float mx = 0.f, my = 0.f, mz = 0.f, mw = 0.f;

    for (int i = i0; i < iend; ++i) {
        const float4* row = in + (size_t)i * N_REC * U4_TOT + u4;
        float sx = 0.f, sy = 0.f, sz = 0.f, sw = 0.f;
#pragma unroll
        for (int r = 0; r < N_REC; ++r) {
            float4 v = __ldcs(row + (size_t)r * U4_TOT);  // evict-first streaming
            sx = fmaf(v.x, wr[r], sx);
            sy = fmaf(v.y, wr[r], sy);
            sz = fmaf(v.z, wr[r], sz);
            sw = fmaf(v.w, wr[r], sw);
        }
        scores[(size_t)i * U4_TOT + u4] = make_float4(sx, sy, sz, sw);  // keep in L2
        mx = fmaxf(mx, sx);
        my = fmaxf(my, sy);
        mz = fmaxf(mz, sz);
        mw = fmaxf(mw, sw);
    }

    // Non-negative floats: int bit ordering == float ordering.
    int* gm = (int*)g_max;
    atomicMax(&gm[u4 * 4 + 0], __float_as_int(mx));
    atomicMax(&gm[u4 * 4 + 1], __float_as_int(my));
    atomicMax(&gm[u4 * 4 + 2], __float_as_int(mz));
    atomicMax(&gm[u4 * 4 + 3], __float_as_int(mw));
}

// Tiny: reciprocal of the chunk's maxes.
__global__ void recip_kernel(int u_base) {
    int u = u_base + blockIdx.x * blockDim.x + threadIdx.x;
    g_inv[u] = 1.0f / g_max[u];
}

// Pass 2 (per user-chunk): out = scores * inv. Reads should hit L2.
// Grid: x = item index, block covers the chunk stripe.
__global__ void __launch_bounds__(CHUNK_U4) normalize_kernel(
    float4* __restrict__ scores, int u4_base)
{
    const int u4 = u4_base + threadIdx.x;
    const size_t idx = (size_t)blockIdx.x * U4_TOT + u4;
    float4 s   = scores[idx];
    float4 inv = *((const float4*)g_inv + u4);
    s.x *= inv.x; s.y *= inv.y; s.z *= inv.z; s.w *= inv.w;
    __stcs(&scores[idx], s);   // final write, no reuse
}

extern "C" void kernel_launch(void* const* d_in, const int* in_sizes, int n_in,
                              void* d_out, int out_size)
{
    const float4* in = (const float4*)d_in[0];   // input [160000, 2048] f32
    const float*  w  = (const float*)d_in[1];    // w [1, 8] f32
    float4* scores = (float4*)d_out;             // [20000, 2048] f32

    // Reset per-run state (graph replays must be deterministic).
    init_max_kernel<<<(N_USERS + 255) / 256, 256>>>();

    for (int c = 0; c < N_CHUNKS; ++c) {
        const int u4_base = c * CHUNK_U4;
        const int u_base  = c * CHUNK_USERS;

        dim3 grid1(1, (N_ITEMS + ITEMS_PER_BLOCK - 1) / ITEMS_PER_BLOCK);
        score_max_kernel<<<grid1, CHUNK_U4>>>(in, w, scores, u4_base);

        recip_kernel<<<CHUNK_USERS / 256, 256>>>(u_base);

        normalize_kernel<<<N_ITEMS, CHUNK_U4>>>(scores, u4_base);
    }
}

// round 3
// speedup vs baseline: 1.0928x; 1.0928x over previous
#include <cuda_runtime.h>
#include <cuda_fp16.h>

// Problem constants
#define N_ITEMS 20000
#define N_REC   8
#define N_USERS 2048
#define U4      (N_USERS / 4)          // 512 float4 columns
#define ITEMS_PER_BLOCK 40             // grid = (2, 500)

// Scratch: fp16 intermediate scores (82 MB), per-user max (float bits), recip.
__device__ __half g_scores[(size_t)N_ITEMS * N_USERS];
__device__ float  g_max[N_USERS];
__device__ float  g_inv[N_USERS];

__global__ void init_max_kernel() {
    int u = blockIdx.x * blockDim.x + threadIdx.x;
    if (u < N_USERS) g_max[u] = 0.0f;
}

// Pass 1: scores[i][u] = sum_r in[i*8+r][u] * w[r]  (fp32 accumulate),
// store fp16 scores, track per-column max in fp32 via atomicMax on bits.
__global__ void __launch_bounds__(256) score_max_kernel(
    const float4* __restrict__ in,   // [N_ITEMS*N_REC, U4]
    const float*  __restrict__ w)    // [8]
{
    const int u4 = blockIdx.x * blockDim.x + threadIdx.x;   // 0..511

    float wr[N_REC];
#pragma unroll
    for (int r = 0; r < N_REC; ++r) wr[r] = __ldg(&w[r]);

    const int i0   = blockIdx.y * ITEMS_PER_BLOCK;
    const int iend = min(i0 + ITEMS_PER_BLOCK, N_ITEMS);

    float mx = 0.f, my = 0.f, mz = 0.f, mw = 0.f;

    uint2* sc16 = (uint2*)g_scores;   // 4 halves per u4 slot

    for (int i = i0; i < iend; ++i) {
        const float4* row = in + (size_t)i * N_REC * U4 + u4;
        float sx = 0.f, sy = 0.f, sz = 0.f, sw = 0.f;
#pragma unroll
        for (int r = 0; r < N_REC; ++r) {
            float4 v = __ldcs(row + (size_t)r * U4);  // read-once streaming
            sx = fmaf(v.x, wr[r], sx);
            sy = fmaf(v.y, wr[r], sy);
            sz = fmaf(v.z, wr[r], sz);
            sw = fmaf(v.w, wr[r], sw);
        }
        __half2 h0 = __floats2half2_rn(sx, sy);
        __half2 h1 = __floats2half2_rn(sz, sw);
        uint2 packed;
        packed.x = *(unsigned int*)&h0;
        packed.y = *(unsigned int*)&h1;
        sc16[(size_t)i * U4 + u4] = packed;

        mx = fmaxf(mx, sx);
        my = fmaxf(my, sy);
        mz = fmaxf(mz, sz);
        mw = fmaxf(mw, sw);
    }

    // Non-negative floats: int bit ordering == float ordering.
    int* gm = (int*)g_max;
    atomicMax(&gm[u4 * 4 + 0], __float_as_int(mx));
    atomicMax(&gm[u4 * 4 + 1], __float_as_int(my));
    atomicMax(&gm[u4 * 4 + 2], __float_as_int(mz));
    atomicMax(&gm[u4 * 4 + 3], __float_as_int(mw));
}

__global__ void recip_kernel() {
    int u = blockIdx.x * blockDim.x + threadIdx.x;
    if (u < N_USERS) g_inv[u] = 1.0f / g_max[u];
}

// Pass 2: out[i][u] = fp16_score[i][u] * inv[u], written f32 to d_out.
__global__ void __launch_bounds__(256) normalize_kernel(float4* __restrict__ out)
{
    int idx = blockIdx.x * blockDim.x + threadIdx.x;   // over N_ITEMS*U4
    if (idx >= N_ITEMS * U4) return;
    int u4 = idx & (U4 - 1);                           // U4 = 512 (pow2)

    uint2 packed = ((const uint2*)g_scores)[idx];
    __half2 h0 = *(__half2*)&packed.x;
    __half2 h1 = *(__half2*)&packed.y;
    float2 f0 = __half22float2(h0);
    float2 f1 = __half22float2(h1);

    float4 inv = *((const float4*)g_inv + u4);
    float4 o;
    o.x = f0.x * inv.x;
    o.y = f0.y * inv.y;
    o.z = f1.x * inv.z;
    o.w = f1.y * inv.w;
    __stcs(&out[idx], o);   // final write, no reuse
}

extern "C" void kernel_launch(void* const* d_in, const int* in_sizes, int n_in,
                              void* d_out, int out_size)
{
    const float4* in = (const float4*)d_in[0];   // input [160000, 2048] f32
    const float*  w  = (const float*)d_in[1];    // w [1, 8] f32
    float4* out = (float4*)d_out;                // [20000, 2048] f32

    // Reset per-run state (graph replays must be deterministic).
    init_max_kernel<<<(N_USERS + 255) / 256, 256>>>();

    dim3 grid1(U4 / 256, (N_ITEMS + ITEMS_PER_BLOCK - 1) / ITEMS_PER_BLOCK);
    score_max_kernel<<<grid1, 256>>>(in, w);

    recip_kernel<<<(N_USERS + 255) / 256, 256>>>();

    int total4 = N_ITEMS * U4;                   // 10,240,000
    normalize_kernel<<<(total4 + 255) / 256, 256>>>(out);
}

// round 4
// speedup vs baseline: 1.2284x; 1.1240x over previous
#include <cuda_runtime.h>
#include <cuda_fp16.h>

// Problem constants
#define N_ITEMS 20000
#define N_REC   8
#define N_USERS 2048
#define U4      (N_USERS / 4)          // 512 float4 columns
#define ITEMS_PER_BLOCK 10             // score grid = 2000 CTAs, contiguous 640KB each

// Scratch: fp16 intermediate scores (82 MB), per-user max (float bits), recip.
__device__ __half g_scores[(size_t)N_ITEMS * N_USERS];
__device__ float  g_max[N_USERS];
__device__ float  g_inv[N_USERS];

__global__ void init_max_kernel() {
    int u = blockIdx.x * blockDim.x + threadIdx.x;
    if (u < N_USERS) g_max[u] = 0.0f;
}

// Pass 1: scores[i][u] = sum_r in[i*8+r][u] * w[r]  (fp32 accumulate),
// store fp16 scores, track per-column max in fp32 via atomicMax on bits.
// One CTA = 512 threads spanning the full user row; 10 items per CTA ->
// each CTA streams a contiguous 640KB input block.
__global__ void __launch_bounds__(512) score_max_kernel(
    const float4* __restrict__ in,   // [N_ITEMS*N_REC, U4]
    const float*  __restrict__ w)    // [8]
{
    const int u4 = threadIdx.x;                       // 0..511, full row

    float wr[N_REC];
#pragma unroll
    for (int r = 0; r < N_REC; ++r) wr[r] = __ldg(&w[r]);

    const int i0   = blockIdx.x * ITEMS_PER_BLOCK;
    const int iend = min(i0 + ITEMS_PER_BLOCK, N_ITEMS);

    float mx = 0.f, my = 0.f, mz = 0.f, mw = 0.f;

    uint2* sc16 = (uint2*)g_scores;   // 4 halves per u4 slot

    for (int i = i0; i < iend; ++i) {
        const float4* row = in + (size_t)i * N_REC * U4 + u4;
        float sx = 0.f, sy = 0.f, sz = 0.f, sw = 0.f;
#pragma unroll
        for (int r = 0; r < N_REC; ++r) {
            float4 v = __ldcs(row + (size_t)r * U4);  // read-once streaming
            sx = fmaf(v.x, wr[r], sx);
            sy = fmaf(v.y, wr[r], sy);
            sz = fmaf(v.z, wr[r], sz);
            sw = fmaf(v.w, wr[r], sw);
        }
        __half2 h0 = __floats2half2_rn(sx, sy);
        __half2 h1 = __floats2half2_rn(sz, sw);
        uint2 packed;
        packed.x = *(unsigned int*)&h0;
        packed.y = *(unsigned int*)&h1;
        sc16[(size_t)i * U4 + u4] = packed;

        mx = fmaxf(mx, sx);
        my = fmaxf(my, sy);
        mz = fmaxf(mz, sz);
        mw = fmaxf(mw, sw);
    }

    // Non-negative floats: int bit ordering == float ordering.
    int* gm = (int*)g_max;
    atomicMax(&gm[u4 * 4 + 0], __float_as_int(mx));
    atomicMax(&gm[u4 * 4 + 1], __float_as_int(my));
    atomicMax(&gm[u4 * 4 + 2], __float_as_int(mz));
    atomicMax(&gm[u4 * 4 + 3], __float_as_int(mw));
}

__global__ void recip_kernel() {
    int u = blockIdx.x * blockDim.x + threadIdx.x;
    if (u < N_USERS) g_inv[u] = 1.0f / g_max[u];
}

// Pass 2: out[i][u] = fp16_score[i][u] * inv[u], written f32 to d_out.
__global__ void __launch_bounds__(256) normalize_kernel(float4* __restrict__ out)
{
    int idx = blockIdx.x * blockDim.x + threadIdx.x;   // over N_ITEMS*U4
    if (idx >= N_ITEMS * U4) return;
    int u4 = idx & (U4 - 1);                           // U4 = 512 (pow2)

    uint2 packed = ((const uint2*)g_scores)[idx];
    __half2 h0 = *(__half2*)&packed.x;
    __half2 h1 = *(__half2*)&packed.y;
    float2 f0 = __half22float2(h0);
    float2 f1 = __half22float2(h1);

    float4 inv = *((const float4*)g_inv + u4);
    float4 o;
    o.x = f0.x * inv.x;
    o.y = f0.y * inv.y;
    o.z = f1.x * inv.z;
    o.w = f1.y * inv.w;
    __stcs(&out[idx], o);   // final write, no reuse
}

extern "C" void kernel_launch(void* const* d_in, const int* in_sizes, int n_in,
                              void* d_out, int out_size)
{
    const float4* in = (const float4*)d_in[0];   // input [160000, 2048] f32
    const float*  w  = (const float*)d_in[1];    // w [1, 8] f32
    float4* out = (float4*)d_out;                // [20000, 2048] f32

    // Reset per-run state (graph replays must be deterministic).
    init_max_kernel<<<(N_USERS + 255) / 256, 256>>>();

    score_max_kernel<<<(N_ITEMS + ITEMS_PER_BLOCK - 1) / ITEMS_PER_BLOCK, 512>>>(in, w);

    recip_kernel<<<(N_USERS + 255) / 256, 256>>>();

    int total4 = N_ITEMS * U4;                   // 10,240,000
    normalize_kernel<<<(total4 + 255) / 256, 256>>>(out);
}

// round 5
// speedup vs baseline: 1.2537x; 1.0206x over previous
#include <cuda_runtime.h>
#include <cuda_fp16.h>

// Problem constants
#define N_ITEMS 20000
#define N_REC   8
#define N_USERS 2048
#define U4      (N_USERS / 4)          // 512 float4 columns
#define ITEMS_PER_BLOCK 16             // score grid = 1250 CTAs, contiguous 1MB each

// Scratch: fp16 intermediate scores (82 MB), per-user max (float bits), recip.
// Note: device globals are zero-initialized at module load; recip_kernel
// re-zeros g_max after use so every graph execution starts from zero.
__device__ __half g_scores[(size_t)N_ITEMS * N_USERS];
__device__ float  g_max[N_USERS];
__device__ float  g_inv[N_USERS];

// Pass 1: scores[i][u] = sum_r in[i*8+r][u] * w[r]  (fp32 accumulate),
// store fp16 scores, track per-column max in fp32 via atomicMax on bits.
// One CTA = 512 threads spanning the full user row; 16 items per CTA ->
// each CTA streams a contiguous 1MB input block.
__global__ void __launch_bounds__(512) score_max_kernel(
    const float4* __restrict__ in,   // [N_ITEMS*N_REC, U4]
    const float*  __restrict__ w)    // [8]
{
    const int u4 = threadIdx.x;                       // 0..511, full row

    float wr[N_REC];
#pragma unroll
    for (int r = 0; r < N_REC; ++r) wr[r] = __ldg(&w[r]);

    const int i0   = blockIdx.x * ITEMS_PER_BLOCK;
    const int iend = min(i0 + ITEMS_PER_BLOCK, N_ITEMS);

    float mx = 0.f, my = 0.f, mz = 0.f, mw = 0.f;

    uint2* sc16 = (uint2*)g_scores;   // 4 halves per u4 slot

    for (int i = i0; i < iend; ++i) {
        const float4* row = in + (size_t)i * N_REC * U4 + u4;
        float sx = 0.f, sy = 0.f, sz = 0.f, sw = 0.f;
#pragma unroll
        for (int r = 0; r < N_REC; ++r) {
            float4 v = __ldcs(row + (size_t)r * U4);  // read-once streaming
            sx = fmaf(v.x, wr[r], sx);
            sy = fmaf(v.y, wr[r], sy);
            sz = fmaf(v.z, wr[r], sz);
            sw = fmaf(v.w, wr[r], sw);
        }
        __half2 h0 = __floats2half2_rn(sx, sy);
        __half2 h1 = __floats2half2_rn(sz, sw);
        uint2 packed;
        packed.x = *(unsigned int*)&h0;
        packed.y = *(unsigned int*)&h1;
        sc16[(size_t)i * U4 + u4] = packed;

        mx = fmaxf(mx, sx);
        my = fmaxf(my, sy);
        mz = fmaxf(mz, sz);
        mw = fmaxf(mw, sw);
    }

    // Non-negative floats: int bit ordering == float ordering.
    int* gm = (int*)g_max;
    atomicMax(&gm[u4 * 4 + 0], __float_as_int(mx));
    atomicMax(&gm[u4 * 4 + 1], __float_as_int(my));
    atomicMax(&gm[u4 * 4 + 2], __float_as_int(mz));
    atomicMax(&gm[u4 * 4 + 3], __float_as_int(mw));
}

// Tiny: inv = 1/max, then reset max to 0 for the next graph execution.
__global__ void recip_kernel() {
    int u = blockIdx.x * blockDim.x + threadIdx.x;
    if (u < N_USERS) {
        g_inv[u] = 1.0f / g_max[u];
        g_max[u] = 0.0f;
    }
}

// Pass 2: out[i][u] = fp16_score[i][u] * inv[u], written f32 to d_out.
__global__ void __launch_bounds__(256) normalize_kernel(float4* __restrict__ out)
{
    int idx = blockIdx.x * blockDim.x + threadIdx.x;   // over N_ITEMS*U4
    if (idx >= N_ITEMS * U4) return;
    int u4 = idx & (U4 - 1);                           // U4 = 512 (pow2)

    uint2 packed = __ldcs((const uint2*)g_scores + idx);  // read-once
    __half2 h0 = *(__half2*)&packed.x;
    __half2 h1 = *(__half2*)&packed.y;
    float2 f0 = __half22float2(h0);
    float2 f1 = __half22float2(h1);

    float4 inv = *((const float4*)g_inv + u4);
    float4 o;
    o.x = f0.x * inv.x;
    o.y = f0.y * inv.y;
    o.z = f1.x * inv.z;
    o.w = f1.y * inv.w;
    __stcs(&out[idx], o);   // final write, no reuse
}

extern "C" void kernel_launch(void* const* d_in, const int* in_sizes, int n_in,
                              void* d_out, int out_size)
{
    const float4* in = (const float4*)d_in[0];   // input [160000, 2048] f32
    const float*  w  = (const float*)d_in[1];    // w [1, 8] f32
    float4* out = (float4*)d_out;                // [20000, 2048] f32

    score_max_kernel<<<(N_ITEMS + ITEMS_PER_BLOCK - 1) / ITEMS_PER_BLOCK, 512>>>(in, w);

    recip_kernel<<<(N_USERS + 255) / 256, 256>>>();

    int total4 = N_ITEMS * U4;                   // 10,240,000
    normalize_kernel<<<(total4 + 255) / 256, 256>>>(out);
}

// round 6
// speedup vs baseline: 1.3032x; 1.0395x over previous
#include <cuda_runtime.h>
#include <cuda_fp16.h>

// Problem constants
#define N_ITEMS 20000
#define N_REC   8
#define N_USERS 2048
#define U4      (N_USERS / 4)          // 512 float4 columns
#define GRID    296                    // 148 SMs x 2 CTAs, co-resident (launch_bounds(512,2))

// Scratch: fp16 intermediate scores (82 MB), per-user max (float bits).
// Device globals are zero-initialized at module load; the kernel's epilogue
// restores g_max and the barrier state to zero for the next graph replay.
__device__ __half   g_scores[(size_t)N_ITEMS * N_USERS];
__device__ float    g_max[N_USERS];
__device__ unsigned g_cnt1 = 0;
__device__ unsigned g_flag1 = 0;
__device__ unsigned g_cnt2 = 0;

__global__ void __launch_bounds__(512, 2) fused_kernel(
    const float4* __restrict__ in,   // [N_ITEMS*N_REC, U4]
    const float*  __restrict__ w,    // [8]
    float4*       __restrict__ out)  // [N_ITEMS, U4]
{
    const int u4 = threadIdx.x;      // 0..511: one float4 column per thread

    float wr[N_REC];
#pragma unroll
    for (int r = 0; r < N_REC; ++r) wr[r] = __ldg(&w[r]);

    uint2* sc16 = (uint2*)g_scores;

    // ---------------- Phase 1: scores + per-column max ----------------
    float mx = 0.f, my = 0.f, mz = 0.f, mw = 0.f;

    for (int i = blockIdx.x; i < N_ITEMS; i += GRID) {
        const float4* row = in + (size_t)i * N_REC * U4 + u4;
        float sx = 0.f, sy = 0.f, sz = 0.f, sw = 0.f;
#pragma unroll
        for (int r = 0; r < N_REC; ++r) {
            float4 v = __ldcs(row + (size_t)r * U4);   // read-once streaming
            sx = fmaf(v.x, wr[r], sx);
            sy = fmaf(v.y, wr[r], sy);
            sz = fmaf(v.z, wr[r], sz);
            sw = fmaf(v.w, wr[r], sw);
        }
        __half2 h0 = __floats2half2_rn(sx, sy);
        __half2 h1 = __floats2half2_rn(sz, sw);
        uint2 packed;
        packed.x = *(unsigned int*)&h0;
        packed.y = *(unsigned int*)&h1;
        sc16[(size_t)i * U4 + u4] = packed;            // default .wb: L2-resident

        mx = fmaxf(mx, sx);
        my = fmaxf(my, sy);
        mz = fmaxf(mz, sz);
        mw = fmaxf(mw, sw);
    }

    // Non-negative floats: int bit ordering == float ordering.
    int* gm = (int*)g_max;
    atomicMax(&gm[u4 * 4 + 0], __float_as_int(mx));
    atomicMax(&gm[u4 * 4 + 1], __float_as_int(my));
    atomicMax(&gm[u4 * 4 + 2], __float_as_int(mz));
    atomicMax(&gm[u4 * 4 + 3], __float_as_int(mw));

    // ---------------- Grid barrier (all 296 CTAs co-resident) ----------------
    __threadfence();      // maxes visible before arrival
    __syncthreads();
    if (threadIdx.x == 0) {
        unsigned t = atomicAdd(&g_cnt1, 1u);
        if (t == GRID - 1) {
            *(volatile unsigned*)&g_flag1 = 1u;        // release
        } else {
            while (*(volatile unsigned*)&g_flag1 == 0u) __nanosleep(32);
        }
        __threadfence();  // acquire: order subsequent g_max reads after flag
    }
    __syncthreads();

    // Per-thread reciprocals of the global column maxes (read via L2).
    float4 m4 = __ldcg((const float4*)g_max + u4);
    float4 inv;
    inv.x = 1.0f / m4.x;
    inv.y = 1.0f / m4.y;
    inv.z = 1.0f / m4.z;
    inv.w = 1.0f / m4.w;

    // ---------------- Phase 2: normalize ----------------
    for (int i = blockIdx.x; i < N_ITEMS; i += GRID) {
        const size_t idx = (size_t)i * U4 + u4;
        uint2 packed = __ldcs((const uint2*)sc16 + idx);  // dead after read
        __half2 h0 = *(__half2*)&packed.x;
        __half2 h1 = *(__half2*)&packed.y;
        float2 f0 = __half22float2(h0);
        float2 f1 = __half22float2(h1);
        float4 o;
        o.x = f0.x * inv.x;
        o.y = f0.y * inv.y;
        o.z = f1.x * inv.z;
        o.w = f1.y * inv.w;
        __stcs(&out[idx], o);                             // final write, no reuse
    }

    // ---------------- Epilogue: last CTA resets state for next replay ----------------
    __shared__ unsigned s_last;
    __syncthreads();
    if (threadIdx.x == 0) {
        __threadfence();
        unsigned t = atomicAdd(&g_cnt2, 1u);
        s_last = (t == GRID - 1) ? 1u : 0u;
    }
    __syncthreads();
    if (s_last) {
        // All CTAs have passed their g_max reads (program order before cnt2 arrive).
        for (int u = threadIdx.x; u < N_USERS; u += 512)
            *(volatile float*)&g_max[u] = 0.0f;
        __syncthreads();
        if (threadIdx.x == 0) {
            *(volatile unsigned*)&g_cnt1  = 0u;
            *(volatile unsigned*)&g_flag1 = 0u;
            *(volatile unsigned*)&g_cnt2  = 0u;
            __threadfence();
        }
    }
}

extern "C" void kernel_launch(void* const* d_in, const int* in_sizes, int n_in,
                              void* d_out, int out_size)
{
    const float4* in = (const float4*)d_in[0];   // input [160000, 2048] f32
    const float*  w  = (const float*)d_in[1];    // w [1, 8] f32
    float4* out = (float4*)d_out;                // [20000, 2048] f32

    fused_kernel<<<GRID, 512>>>(in, w, out);
}

// round 7
// speedup vs baseline: 1.3299x; 1.0205x over previous
#include <cuda_runtime.h>
#include <cuda_fp16.h>

// Problem constants
#define N_ITEMS 20000
#define N_REC   8
#define N_USERS 2048
#define U4      (N_USERS / 4)          // 512 float4 columns
#define GRID    296                    // 148 SMs x 2 CTAs, co-resident (launch_bounds(512,2))

// Scratch: fp16 intermediate scores (82 MB, 128B-aligned for L2 line discard),
// per-user max (float bits). Device globals are zero-initialized at load; the
// kernel epilogue restores g_max and barrier state to zero for the next replay.
__device__ __align__(128) __half g_scores[(size_t)N_ITEMS * N_USERS];
__device__ float    g_max[N_USERS];
__device__ unsigned g_cnt1 = 0;
__device__ unsigned g_flag1 = 0;
__device__ unsigned g_cnt2 = 0;

__global__ void __launch_bounds__(512, 2) fused_kernel(
    const float4* __restrict__ in,   // [N_ITEMS*N_REC, U4]
    const float*  __restrict__ w,    // [8]
    float4*       __restrict__ out)  // [N_ITEMS, U4]
{
    const int u4 = threadIdx.x;      // 0..511: one float4 column per thread

    float wr[N_REC];
#pragma unroll
    for (int r = 0; r < N_REC; ++r) wr[r] = __ldg(&w[r]);

    uint2* sc16 = (uint2*)g_scores;

    // ---------------- Phase 1: scores + per-column max ----------------
    float mx = 0.f, my = 0.f, mz = 0.f, mw = 0.f;

    for (int i = blockIdx.x; i < N_ITEMS; i += GRID) {
        const float4* row = in + (size_t)i * N_REC * U4 + u4;
        float sx = 0.f, sy = 0.f, sz = 0.f, sw = 0.f;
#pragma unroll
        for (int r = 0; r < N_REC; ++r) {
            float4 v = __ldcs(row + (size_t)r * U4);   // read-once streaming
            sx = fmaf(v.x, wr[r], sx);
            sy = fmaf(v.y, wr[r], sy);
            sz = fmaf(v.z, wr[r], sz);
            sw = fmaf(v.w, wr[r], sw);
        }
        __half2 h0 = __floats2half2_rn(sx, sy);
        __half2 h1 = __floats2half2_rn(sz, sw);
        uint2 packed;
        packed.x = *(unsigned int*)&h0;
        packed.y = *(unsigned int*)&h1;
        sc16[(size_t)i * U4 + u4] = packed;            // default .wb: L2-resident

        mx = fmaxf(mx, sx);
        my = fmaxf(my, sy);
        mz = fmaxf(mz, sz);
        mw = fmaxf(mw, sw);
    }

    // Non-negative floats: int bit ordering == float ordering.
    int* gm = (int*)g_max;
    atomicMax(&gm[u4 * 4 + 0], __float_as_int(mx));
    atomicMax(&gm[u4 * 4 + 1], __float_as_int(my));
    atomicMax(&gm[u4 * 4 + 2], __float_as_int(mz));
    atomicMax(&gm[u4 * 4 + 3], __float_as_int(mw));

    // ---------------- Grid barrier (all 296 CTAs co-resident) ----------------
    __threadfence();      // maxes visible before arrival
    __syncthreads();
    if (threadIdx.x == 0) {
        unsigned t = atomicAdd(&g_cnt1, 1u);
        if (t == GRID - 1) {
            *(volatile unsigned*)&g_flag1 = 1u;        // release
        } else {
            while (*(volatile unsigned*)&g_flag1 == 0u) __nanosleep(32);
        }
        __threadfence();  // acquire: order subsequent g_max reads after flag
    }
    __syncthreads();

    // Per-thread reciprocals of the global column maxes (read via L2).
    float4 m4 = __ldcg((const float4*)g_max + u4);
    float4 inv;
    inv.x = 1.0f / m4.x;
    inv.y = 1.0f / m4.y;
    inv.z = 1.0f / m4.z;
    inv.w = 1.0f / m4.w;

    // ---------------- Phase 2: normalize (reverse order: hottest lines first) ----------------
    // Items for this CTA: i = blockIdx.x + k*GRID, k = 0..kmax.
    const int kmax = (N_ITEMS - 1 - blockIdx.x) / GRID;
    for (int k = kmax; k >= 0; --k) {
        const int i = blockIdx.x + k * GRID;
        const size_t idx = (size_t)i * U4 + u4;
        uint2 packed = __ldcs((const uint2*)sc16 + idx);  // dead after read
        __half2 h0 = *(__half2*)&packed.x;
        __half2 h1 = *(__half2*)&packed.y;
        float2 f0 = __half22float2(h0);
        float2 f1 = __half22float2(h1);
        float4 o;
        o.x = f0.x * inv.x;
        o.y = f0.y * inv.y;
        o.z = f1.x * inv.z;
        o.w = f1.y * inv.w;
        __stcs(&out[idx], o);                             // final write, no reuse

        // Scratch line is dead: drop it from L2 without writeback.
        // 16 consecutive u4 threads share one 128B line and sit in the same
        // warp; their loads completed (values consumed above) before the
        // elected lane issues the discard.
        if ((u4 & 15) == 0) {
            const uint2* line = sc16 + idx;   // 128B-aligned (u4 mult of 16)
            asm volatile("discard.global.L2 [%0], 128;" :: "l"(line) : "memory");
        }
    }

    // ---------------- Epilogue: last CTA resets state for next replay ----------------
    __shared__ unsigned s_last;
    __syncthreads();
    if (threadIdx.x == 0) {
        __threadfence();
        unsigned t = atomicAdd(&g_cnt2, 1u);
        s_last = (t == GRID - 1) ? 1u : 0u;
    }
    __syncthreads();
    if (s_last) {
        // All CTAs have passed their g_max reads (program order before cnt2 arrive).
        for (int u = threadIdx.x; u < N_USERS; u += 512)
            *(volatile float*)&g_max[u] = 0.0f;
        __syncthreads();
        if (threadIdx.x == 0) {
            *(volatile unsigned*)&g_cnt1  = 0u;
            *(volatile unsigned*)&g_flag1 = 0u;
            *(volatile unsigned*)&g_cnt2  = 0u;
            __threadfence();
        }
    }
}

extern "C" void kernel_launch(void* const* d_in, const int* in_sizes, int n_in,
                              void* d_out, int out_size)
{
    const float4* in = (const float4*)d_in[0];   // input [160000, 2048] f32
    const float*  w  = (const float*)d_in[1];    // w [1, 8] f32
    float4* out = (float4*)d_out;                // [20000, 2048] f32

    fused_kernel<<<GRID, 512>>>(in, w, out);
}